// round 5
// baseline (speedup 1.0000x reference)
#include <cuda_runtime.h>
#include <cuda_bf16.h>
#include <cstdint>

// Problem constants (fixed by the reference)
#define NNODES 100000
#define FDIM   128
#define HID    128
#define NCLS   40
#define EMAX   1600000
#define NEG_SLOPE 0.2f
#define BN_EPS 1e-5f

#define SCAN_BLK 1024
#define NSCANBLK ((NNODES + SCAN_BLK - 1) / SCAN_BLK)   // 98

// ----------------------------------------------------------------------------
// Device scratch (static globals — no runtime allocation allowed)
// ----------------------------------------------------------------------------
__device__ float g_h[NNODES * HID];      // linear output of current layer
__device__ float g_out[NNODES * HID];    // GAT aggregation output (pre-BN)
__device__ float g_as[NNODES];
__device__ float g_ad[NNODES];
__device__ float g_stats[2 * HID];       // per-channel sum / sumsq
__device__ float g_bnsc[HID];            // folded BN scale (gamma * rstd)
__device__ float g_bnsh[HID];            // folded BN shift (beta - mean*scale)

// CSR (dst -> list of src), rebuilt every launch (deterministic)
__device__ int g_deg[NNODES];
__device__ int g_fill[NNODES];
__device__ int g_rowptr[NNODES + 1];
__device__ int g_blocksum[128];
__device__ int g_csrc[EMAX];

// ----------------------------------------------------------------------------
__device__ __forceinline__ float lrelu(float x) {
    return x > 0.f ? x : NEG_SLOPE * x;
}

__device__ __forceinline__ unsigned f2tf32(float f) {
    unsigned r;
    asm("cvt.rna.tf32.f32 %0, %1;" : "=r"(r) : "f"(f));
    return r;
}

__device__ __forceinline__ void mma_tf32(float d[4], const unsigned a[4],
                                         const unsigned b[2], const float c[4]) {
    asm volatile(
        "mma.sync.aligned.m16n8k8.row.col.f32.tf32.tf32.f32 "
        "{%0,%1,%2,%3}, {%4,%5,%6,%7}, {%8,%9}, {%10,%11,%12,%13};"
        : "=f"(d[0]), "=f"(d[1]), "=f"(d[2]), "=f"(d[3])
        : "r"(a[0]), "r"(a[1]), "r"(a[2]), "r"(a[3]),
          "r"(b[0]), "r"(b[1]),
          "f"(c[0]), "f"(c[1]), "f"(c[2]), "f"(c[3]));
}

// Split a float into tf32 hi + tf32 residual (Markidis)
__device__ __forceinline__ uint2 split_tf32(float v) {
    unsigned hi = f2tf32(v);
    float lo = v - __uint_as_float(hi);
    return make_uint2(hi, f2tf32(lo));
}

// ----------------------------------------------------------------------------
// Split-tf32 tensor-core GEMM: C = A @ B (+bias), fp32-accurate (3-term MMA).
// Optional BNA: A elements pass through per-channel BN (scale/shift) + ReLU.
// ----------------------------------------------------------------------------
template<int BM, int BN, int NWM, int NWN, bool BIAS, bool NGUARD, bool BNA>
__global__ void mma_gemm_kernel(const float* __restrict__ A,
                                const float* __restrict__ B,
                                const float* __restrict__ bias,
                                float* __restrict__ C,
                                int M, int K, int NC)
{
    constexpr int BK = 16;
    constexpr int THREADS = NWM * NWN * 32;
    constexpr int WM = BM / NWM;
    constexpr int WN = BN / NWN;
    constexpr int MT = WM / 16;
    constexpr int NT = WN / 8;

    __shared__ uint2 As[BK][BM + 4];   // {hi,lo} tf32 bits, k-major
    __shared__ uint2 Bs[BK][BN + 4];

    const int tid    = threadIdx.x;
    const int warpId = tid >> 5;
    const int lane   = tid & 31;
    const int warpM  = warpId % NWM;
    const int warpN  = warpId / NWM;
    const int t      = lane & 3;
    const int g      = lane >> 2;
    const int rowBase = blockIdx.x * BM;

    float acc[MT][NT][4];
#pragma unroll
    for (int i = 0; i < MT; i++)
#pragma unroll
        for (int j = 0; j < NT; j++)
#pragma unroll
            for (int r = 0; r < 4; r++) acc[i][j][r] = 0.f;

    for (int k0 = 0; k0 < K; k0 += BK) {
#pragma unroll
        for (int i = tid; i < BM * BK; i += THREADS) {
            int m = i / BK, k = i % BK;
            int gr = rowBase + m;
            float v = (gr < M) ? A[(size_t)gr * K + k0 + k] : 0.f;
            if (BNA) {
                int c = k0 + k;
                v = fmaxf(v * g_bnsc[c] + g_bnsh[c], 0.f);
            }
            As[k][m] = split_tf32(v);
        }
#pragma unroll
        for (int i = tid; i < BK * BN; i += THREADS) {
            int k = i / BN, n = i % BN;
            float v = (!NGUARD || n < NC) ? B[(size_t)(k0 + k) * NC + n] : 0.f;
            Bs[k][n] = split_tf32(v);
        }
        __syncthreads();

#pragma unroll
        for (int ks = 0; ks < BK; ks += 8) {
            unsigned ah[MT][4], al[MT][4];
#pragma unroll
            for (int mt = 0; mt < MT; mt++) {
                int mr = warpM * WM + mt * 16;
                uint2 v0 = As[ks + t][mr + g];
                uint2 v1 = As[ks + t][mr + g + 8];
                uint2 v2 = As[ks + t + 4][mr + g];
                uint2 v3 = As[ks + t + 4][mr + g + 8];
                ah[mt][0] = v0.x; al[mt][0] = v0.y;
                ah[mt][1] = v1.x; al[mt][1] = v1.y;
                ah[mt][2] = v2.x; al[mt][2] = v2.y;
                ah[mt][3] = v3.x; al[mt][3] = v3.y;
            }
            unsigned bh[NT][2], bl[NT][2];
#pragma unroll
            for (int nt = 0; nt < NT; nt++) {
                int nc0 = warpN * WN + nt * 8;
                uint2 w0 = Bs[ks + t][nc0 + g];
                uint2 w1 = Bs[ks + t + 4][nc0 + g];
                bh[nt][0] = w0.x; bl[nt][0] = w0.y;
                bh[nt][1] = w1.x; bl[nt][1] = w1.y;
            }
#pragma unroll
            for (int mt = 0; mt < MT; mt++)
#pragma unroll
                for (int nt = 0; nt < NT; nt++) {
                    mma_tf32(acc[mt][nt], ah[mt], bl[nt], acc[mt][nt]);
                    mma_tf32(acc[mt][nt], al[mt], bh[nt], acc[mt][nt]);
                    mma_tf32(acc[mt][nt], ah[mt], bh[nt], acc[mt][nt]);
                }
        }
        __syncthreads();
    }

#pragma unroll
    for (int mt = 0; mt < MT; mt++) {
#pragma unroll
        for (int nt = 0; nt < NT; nt++) {
            int col = warpN * WN + nt * 8 + 2 * t;
            if (NGUARD && col >= NC) continue;
            float b0 = 0.f, b1 = 0.f;
            if (BIAS) { b0 = bias[col]; b1 = bias[col + 1]; }
            int row0 = rowBase + warpM * WM + mt * 16 + g;
            if (row0 < M) {
                float2 v = make_float2(acc[mt][nt][0] + b0, acc[mt][nt][1] + b1);
                *(float2*)(C + (size_t)row0 * NC + col) = v;
            }
            int row1 = row0 + 8;
            if (row1 < M) {
                float2 v = make_float2(acc[mt][nt][2] + b0, acc[mt][nt][3] + b1);
                *(float2*)(C + (size_t)row1 * NC + col) = v;
            }
        }
    }
}

// ----------------------------------------------------------------------------
// CSR build kernels (edge indices are int32 — JAX x64 is disabled by default)
// ----------------------------------------------------------------------------
__global__ void csr_zero_kernel()
{
    int i = blockIdx.x * blockDim.x + threadIdx.x;
    if (i < NNODES) { g_deg[i] = 0; g_fill[i] = 0; }
}

__global__ void csr_count_kernel(const int* __restrict__ dstp, int E)
{
    int e = blockIdx.x * blockDim.x + threadIdx.x;
    if (e < E) atomicAdd(&g_deg[dstp[e]], 1);
}

__global__ void csr_scan_block_kernel()
{
    __shared__ int s[SCAN_BLK];
    int t = threadIdx.x;
    int i = blockIdx.x * SCAN_BLK + t;
    int v = (i < NNODES) ? g_deg[i] : 0;
    s[t] = v;
    __syncthreads();
#pragma unroll
    for (int off = 1; off < SCAN_BLK; off <<= 1) {
        int x = (t >= off) ? s[t - off] : 0;
        __syncthreads();
        s[t] += x;
        __syncthreads();
    }
    if (i < NNODES) g_rowptr[i] = s[t] - v;       // exclusive within block
    if (t == SCAN_BLK - 1) g_blocksum[blockIdx.x] = s[t];
}

__global__ void csr_scan_tops_kernel(int nblocks, int E)
{
    __shared__ int s[128];
    int t = threadIdx.x;                            // 128 threads
    int v = (t < nblocks) ? g_blocksum[t] : 0;
    s[t] = v;
    __syncthreads();
#pragma unroll
    for (int off = 1; off < 128; off <<= 1) {
        int x = (t >= off) ? s[t - off] : 0;
        __syncthreads();
        s[t] += x;
        __syncthreads();
    }
    g_blocksum[t] = s[t] - v;                       // exclusive block offsets
    if (t == 0) g_rowptr[NNODES] = E;
}

__global__ void csr_addoff_kernel()
{
    int i = blockIdx.x * SCAN_BLK + threadIdx.x;
    if (i < NNODES) g_rowptr[i] += g_blocksum[blockIdx.x];
}

__global__ void csr_fill_kernel(const int* __restrict__ srcp,
                                const int* __restrict__ dstp, int E)
{
    int e = blockIdx.x * blockDim.x + threadIdx.x;
    if (e >= E) return;
    int d = dstp[e];
    int p = atomicAdd(&g_fill[d], 1);
    g_csrc[g_rowptr[d] + p] = srcp[e];
}

// ----------------------------------------------------------------------------
// Per-node attention dots (warp per node) + zero BN stats for this layer
// ----------------------------------------------------------------------------
__global__ void alphadot_kernel(const float* __restrict__ h,
                                const float* __restrict__ a_s,
                                const float* __restrict__ a_d)
{
    int gtid = blockIdx.x * blockDim.x + threadIdx.x;
    if (gtid < 2 * HID) g_stats[gtid] = 0.f;

    int n = gtid >> 5;
    int lane = gtid & 31;
    if (n >= NNODES) return;

    float4 hv = *(const float4*)(h + (size_t)n * HID + lane * 4);
    float4 s4 = *(const float4*)(a_s + lane * 4);
    float4 d4 = *(const float4*)(a_d + lane * 4);
    float ss = hv.x * s4.x + hv.y * s4.y + hv.z * s4.z + hv.w * s4.w;
    float sd = hv.x * d4.x + hv.y * d4.y + hv.z * d4.z + hv.w * d4.w;
#pragma unroll
    for (int o = 16; o > 0; o >>= 1) {
        ss += __shfl_xor_sync(0xffffffffu, ss, o);
        sd += __shfl_xor_sync(0xffffffffu, sd, o);
    }
    if (lane == 0) {
        g_as[n] = ss;
        g_ad[n] = sd;
    }
}

// ----------------------------------------------------------------------------
// Fused segment softmax + aggregation + bias + BN-stats accumulation.
// One warp per destination node; 8 nodes per 256-thread block.
// Unnormalized accumulate (divide by exp-sum at the end).
// One exp PER EDGE (lane-parallel), shfl-broadcast to all lanes.
// ----------------------------------------------------------------------------
__global__ void gat_node_kernel(const float* __restrict__ h,
                                const float* __restrict__ bias)
{
    __shared__ float s_sum[HID];
    __shared__ float s_sq[HID];

    const int tid  = threadIdx.x;
    const int lane = tid & 31;
    const int n    = (blockIdx.x * blockDim.x + tid) >> 5;

    for (int i = tid; i < HID; i += 256) { s_sum[i] = 0.f; s_sq[i] = 0.f; }
    __syncthreads();

    float4 outv = make_float4(0.f, 0.f, 0.f, 0.f);
    bool active = (n < NNODES);

    if (active) {
        const int beg = g_rowptr[n];
        const int end = g_rowptr[n + 1];
        const float adn = g_ad[n];
        const float selfs = lrelu(g_as[n] + adn);

        // Pass 1: segment max (self-loop seeded)
        float m = selfs;
        for (int i = beg + lane; i < end; i += 32)
            m = fmaxf(m, lrelu(g_as[g_csrc[i]] + adn));
#pragma unroll
        for (int o = 16; o > 0; o >>= 1)
            m = fmaxf(m, __shfl_xor_sync(0xffffffffu, m, o));

        // Pass 2: fused exp-sum + unnormalized accumulate.
        float esum = 0.f;
        float4 acc = make_float4(0.f, 0.f, 0.f, 0.f);
        int base = beg;
        for (; base + 32 <= end; base += 32) {
            int idx = base + lane;
            int s = g_csrc[idx];
            float e = __expf(lrelu(g_as[s] + adn) - m);
            esum += e;
#pragma unroll
            for (int j = 0; j < 32; j++) {
                float ej = __shfl_sync(0xffffffffu, e, j);
                int   sj = __shfl_sync(0xffffffffu, s, j);
                float4 v = *(const float4*)(h + (size_t)sj * HID + (lane << 2));
                acc.x += ej * v.x; acc.y += ej * v.y;
                acc.z += ej * v.z; acc.w += ej * v.w;
            }
        }
        if (base < end) {
            int idx = base + lane;
            float e = 0.f; int s = 0;
            if (idx < end) {
                s = g_csrc[idx];
                e = __expf(lrelu(g_as[s] + adn) - m);
            }
            esum += e;
            int cnt = end - base;
            for (int j = 0; j < cnt; j++) {
                float ej = __shfl_sync(0xffffffffu, e, j);
                int   sj = __shfl_sync(0xffffffffu, s, j);
                float4 v = *(const float4*)(h + (size_t)sj * HID + (lane << 2));
                acc.x += ej * v.x; acc.y += ej * v.y;
                acc.z += ej * v.z; acc.w += ej * v.w;
            }
        }
#pragma unroll
        for (int o = 16; o > 0; o >>= 1)
            esum += __shfl_xor_sync(0xffffffffu, esum, o);

        float eself = __expf(selfs - m);
        float inv = __fdividef(1.f, esum + eself);

        float4 hv = *(const float4*)(h + (size_t)n * HID + (lane << 2));
        float4 bv = *(const float4*)(bias + (lane << 2));
        outv.x = (acc.x + eself * hv.x) * inv + bv.x;
        outv.y = (acc.y + eself * hv.y) * inv + bv.y;
        outv.z = (acc.z + eself * hv.z) * inv + bv.z;
        outv.w = (acc.w + eself * hv.w) * inv + bv.w;
        *(float4*)(g_out + (size_t)n * HID + (lane << 2)) = outv;

        // Accumulate BN stats into shared
        int c0 = lane << 2;
        atomicAdd(&s_sum[c0 + 0], outv.x);
        atomicAdd(&s_sum[c0 + 1], outv.y);
        atomicAdd(&s_sum[c0 + 2], outv.z);
        atomicAdd(&s_sum[c0 + 3], outv.w);
        atomicAdd(&s_sq[c0 + 0], outv.x * outv.x);
        atomicAdd(&s_sq[c0 + 1], outv.y * outv.y);
        atomicAdd(&s_sq[c0 + 2], outv.z * outv.z);
        atomicAdd(&s_sq[c0 + 3], outv.w * outv.w);
    }

    __syncthreads();
    if (tid < HID)
        atomicAdd(&g_stats[tid], s_sum[tid]);
    else
        atomicAdd(&g_stats[tid], s_sq[tid - HID]);
}

// ----------------------------------------------------------------------------
// Finalize BN: fold mean/var/gamma/beta into per-channel scale+shift
// ----------------------------------------------------------------------------
__global__ void bnfinal_kernel(const float* __restrict__ gamma,
                               const float* __restrict__ beta)
{
    int c = threadIdx.x;                 // 128 threads
    float inv_n = 1.0f / (float)NNODES;
    float mean = g_stats[c] * inv_n;
    float var  = g_stats[HID + c] * inv_n - mean * mean;
    float sc = gamma[c] * rsqrtf(var + BN_EPS);
    g_bnsc[c] = sc;
    g_bnsh[c] = beta[c] - mean * sc;
}

// ----------------------------------------------------------------------------
extern "C" void kernel_launch(void* const* d_in, const int* in_sizes, int n_in,
                              void* d_out, int out_size)
{
    const float* x    = (const float*)d_in[0];
    const int*   ei   = (const int*)d_in[1];     // int32 (JAX x64 disabled)
    const float* W1   = (const float*)d_in[2];
    const float* as1  = (const float*)d_in[3];
    const float* ad1  = (const float*)d_in[4];
    const float* b1   = (const float*)d_in[5];
    const float* g1   = (const float*)d_in[6];
    const float* be1  = (const float*)d_in[7];
    const float* W2   = (const float*)d_in[8];
    const float* as2  = (const float*)d_in[9];
    const float* ad2  = (const float*)d_in[10];
    const float* b2   = (const float*)d_in[11];
    const float* g2   = (const float*)d_in[12];
    const float* be2  = (const float*)d_in[13];
    const float* Wc   = (const float*)d_in[14];
    const float* bc   = (const float*)d_in[15];
    float*       out  = (float*)d_out;

    int E = in_sizes[1] / 2;
    if (E > EMAX) E = EMAX;
    const int* srcp = ei;
    const int* dstp = ei + E;

    float* d_h;
    cudaGetSymbolAddress((void**)&d_h, g_h);
    float* d_agg;
    cudaGetSymbolAddress((void**)&d_agg, g_out);

    // ---- Build CSR (dst -> srcs), once per launch ----
    csr_zero_kernel<<<(NNODES + 255) / 256, 256>>>();
    csr_count_kernel<<<(E + 255) / 256, 256>>>(dstp, E);
    csr_scan_block_kernel<<<NSCANBLK, SCAN_BLK>>>();
    csr_scan_tops_kernel<<<1, 128>>>(NSCANBLK, E);
    csr_addoff_kernel<<<NSCANBLK, SCAN_BLK>>>();
    csr_fill_kernel<<<(E + 255) / 256, 256>>>(srcp, dstp, E);

    const int gemm_grid = (NNODES + 127) / 128;
    const int node_grid = (NNODES * 32 + 255) / 256;

    // ---- Layer 1 ----
    mma_gemm_kernel<128, 128, 4, 2, false, false, false><<<gemm_grid, 256>>>(
        x, W1, nullptr, d_h, NNODES, FDIM, HID);
    alphadot_kernel<<<node_grid, 256>>>(d_h, as1, ad1);
    gat_node_kernel<<<node_grid, 256>>>(d_h, b1);
    bnfinal_kernel<<<1, 128>>>(g1, be1);

    // ---- Layer 2 (A = BN(out1) applied inline in GEMM) ----
    mma_gemm_kernel<128, 128, 4, 2, false, false, true><<<gemm_grid, 256>>>(
        d_agg, W2, nullptr, d_h, NNODES, HID, HID);
    alphadot_kernel<<<node_grid, 256>>>(d_h, as2, ad2);
    gat_node_kernel<<<node_grid, 256>>>(d_h, b2);
    bnfinal_kernel<<<1, 128>>>(g2, be2);

    // ---- Classifier: out = BN(out2) @ Wc + bc ----
    mma_gemm_kernel<128, 64, 4, 2, true, true, true><<<gemm_grid, 256>>>(
        d_agg, Wc, bc, out, NNODES, HID, NCLS);
}

// round 6
// speedup vs baseline: 1.3543x; 1.3543x over previous
#include <cuda_runtime.h>
#include <cuda_bf16.h>
#include <cstdint>

// Problem constants (fixed by the reference)
#define NNODES 100000
#define FDIM   128
#define HID    128
#define NCLS   40
#define EMAX   1600000
#define NEG_SLOPE 0.2f
#define BN_EPS 1e-5f

#define SCAN_BLK 1024
#define NSCANBLK ((NNODES + SCAN_BLK - 1) / SCAN_BLK)   // 98

// ----------------------------------------------------------------------------
// Device scratch (static globals — no runtime allocation allowed)
// ----------------------------------------------------------------------------
__device__ float g_h[NNODES * HID];      // linear output of current layer
__device__ float g_out[NNODES * HID];    // GAT aggregation output (pre-BN)
__device__ float g_as[NNODES];
__device__ float g_ad[NNODES];
__device__ float g_stats[2 * HID];       // per-channel sum / sumsq
__device__ float g_bnsc[HID];            // folded BN scale (gamma * rstd)
__device__ float g_bnsh[HID];            // folded BN shift (beta - mean*scale)

// CSR (dst -> list of src), rebuilt every launch (deterministic)
__device__ int g_deg[NNODES];
__device__ int g_fill[NNODES];
__device__ int g_rowptr[NNODES + 1];
__device__ int g_blocksum[128];
__device__ int g_csrc[EMAX];

// ----------------------------------------------------------------------------
__device__ __forceinline__ float lrelu(float x) {
    return x > 0.f ? x : NEG_SLOPE * x;
}

__device__ __forceinline__ unsigned bfpack(float lo, float hi) {
    __nv_bfloat162 p = __floats2bfloat162_rn(lo, hi);
    return *(unsigned*)&p;
}

// bf16 mma m16n8k16: d = a*b + c
__device__ __forceinline__ void mma_bf16(float d[4], const unsigned a[4],
                                         const unsigned b[2], const float c[4]) {
    asm volatile(
        "mma.sync.aligned.m16n8k16.row.col.f32.bf16.bf16.f32 "
        "{%0,%1,%2,%3}, {%4,%5,%6,%7}, {%8,%9}, {%10,%11,%12,%13};"
        : "=f"(d[0]), "=f"(d[1]), "=f"(d[2]), "=f"(d[3])
        : "r"(a[0]), "r"(a[1]), "r"(a[2]), "r"(a[3]),
          "r"(b[0]), "r"(b[1]),
          "f"(c[0]), "f"(c[1]), "f"(c[2]), "f"(c[3]));
}

// ----------------------------------------------------------------------------
// bf16x3 tensor-core GEMM: C = A @ B (+bias), ~2^-17 accurate.
// A,B split into bf16 hi + bf16 residual; acc += a0b0 + a0b1 + a1b0.
// Optional BNA: A passes through per-channel BN scale/shift + ReLU.
// Smem layout: kpair-major; uint2 = {pack(hi_k, hi_k1), pack(lo_k, lo_k1)}.
// ----------------------------------------------------------------------------
template<int BM, int BN, int NWM, int NWN, bool BIAS, bool NGUARD, bool BNA>
__global__ void mma_gemm_kernel(const float* __restrict__ A,
                                const float* __restrict__ B,
                                const float* __restrict__ bias,
                                float* __restrict__ C,
                                int M, int K, int NC)
{
    constexpr int BK = 16;                // k per mainloop step (8 kpairs)
    constexpr int THREADS = NWM * NWN * 32;
    constexpr int WM = BM / NWM;
    constexpr int WN = BN / NWN;
    constexpr int MT = WM / 16;
    constexpr int NT = WN / 8;

    __shared__ uint2 As[8][BM + 4];
    __shared__ uint2 Bs[8][BN + 4];

    const int tid    = threadIdx.x;
    const int warpId = tid >> 5;
    const int lane   = tid & 31;
    const int warpM  = warpId % NWM;
    const int warpN  = warpId / NWM;
    const int t      = lane & 3;
    const int g      = lane >> 2;
    const int rowBase = blockIdx.x * BM;

    float acc[MT][NT][4];
#pragma unroll
    for (int i = 0; i < MT; i++)
#pragma unroll
        for (int j = 0; j < NT; j++)
#pragma unroll
            for (int r = 0; r < 4; r++) acc[i][j][r] = 0.f;

    for (int k0 = 0; k0 < K; k0 += BK) {
        // A tile: thread handles (m, kpair), loads float2 along k
#pragma unroll
        for (int i = tid; i < BM * 8; i += THREADS) {
            int m = i >> 3, kp = i & 7;
            int gr = rowBase + m;
            float2 va = make_float2(0.f, 0.f);
            if (gr < M)
                va = *(const float2*)(A + (size_t)gr * K + k0 + 2 * kp);
            if (BNA) {
                int c = k0 + 2 * kp;
                va.x = fmaxf(va.x * g_bnsc[c] + g_bnsh[c], 0.f);
                va.y = fmaxf(va.y * g_bnsc[c + 1] + g_bnsh[c + 1], 0.f);
            }
            float x0 = __bfloat162float(__float2bfloat16_rn(va.x));
            float y0 = __bfloat162float(__float2bfloat16_rn(va.y));
            As[kp][m] = make_uint2(bfpack(x0, y0), bfpack(va.x - x0, va.y - y0));
        }
        // B tile: thread handles (kpair, n), loads the two k rows
#pragma unroll
        for (int i = tid; i < 8 * BN; i += THREADS) {
            int kp = i / BN, n = i % BN;
            float be = 0.f, bo = 0.f;
            if (!NGUARD || n < NC) {
                be = B[(size_t)(k0 + 2 * kp) * NC + n];
                bo = B[(size_t)(k0 + 2 * kp + 1) * NC + n];
            }
            float e0 = __bfloat162float(__float2bfloat16_rn(be));
            float o0 = __bfloat162float(__float2bfloat16_rn(bo));
            Bs[kp][n] = make_uint2(bfpack(e0, o0), bfpack(be - e0, bo - o0));
        }
        __syncthreads();

        unsigned a0[MT][4], a1[MT][4];
#pragma unroll
        for (int mt = 0; mt < MT; mt++) {
            int mr = warpM * WM + mt * 16;
            uint2 v0 = As[t][mr + g];
            uint2 v1 = As[t][mr + g + 8];
            uint2 v2 = As[t + 4][mr + g];
            uint2 v3 = As[t + 4][mr + g + 8];
            a0[mt][0] = v0.x; a1[mt][0] = v0.y;
            a0[mt][1] = v1.x; a1[mt][1] = v1.y;
            a0[mt][2] = v2.x; a1[mt][2] = v2.y;
            a0[mt][3] = v3.x; a1[mt][3] = v3.y;
        }
        unsigned b0[NT][2], b1[NT][2];
#pragma unroll
        for (int nt = 0; nt < NT; nt++) {
            int nc0 = warpN * WN + nt * 8;
            uint2 w0 = Bs[t][nc0 + g];
            uint2 w1 = Bs[t + 4][nc0 + g];
            b0[nt][0] = w0.x; b1[nt][0] = w0.y;
            b0[nt][1] = w1.x; b1[nt][1] = w1.y;
        }
#pragma unroll
        for (int mt = 0; mt < MT; mt++)
#pragma unroll
            for (int nt = 0; nt < NT; nt++) {
                mma_bf16(acc[mt][nt], a0[mt], b1[nt], acc[mt][nt]);
                mma_bf16(acc[mt][nt], a1[mt], b0[nt], acc[mt][nt]);
                mma_bf16(acc[mt][nt], a0[mt], b0[nt], acc[mt][nt]);
            }
        __syncthreads();
    }

#pragma unroll
    for (int mt = 0; mt < MT; mt++) {
#pragma unroll
        for (int nt = 0; nt < NT; nt++) {
            int col = warpN * WN + nt * 8 + 2 * t;
            if (NGUARD && col >= NC) continue;
            float b0v = 0.f, b1v = 0.f;
            if (BIAS) { b0v = bias[col]; b1v = bias[col + 1]; }
            int row0 = rowBase + warpM * WM + mt * 16 + g;
            if (row0 < M) {
                float2 v = make_float2(acc[mt][nt][0] + b0v, acc[mt][nt][1] + b1v);
                *(float2*)(C + (size_t)row0 * NC + col) = v;
            }
            int row1 = row0 + 8;
            if (row1 < M) {
                float2 v = make_float2(acc[mt][nt][2] + b0v, acc[mt][nt][3] + b1v);
                *(float2*)(C + (size_t)row1 * NC + col) = v;
            }
        }
    }
}

// ----------------------------------------------------------------------------
// CSR build kernels (edge indices are int32)
// ----------------------------------------------------------------------------
__global__ void csr_zero_kernel()
{
    int i = blockIdx.x * blockDim.x + threadIdx.x;
    if (i < NNODES) { g_deg[i] = 0; g_fill[i] = 0; }
}

__global__ void csr_count_kernel(const int* __restrict__ dstp, int E)
{
    int e = blockIdx.x * blockDim.x + threadIdx.x;
    if (e < E) atomicAdd(&g_deg[dstp[e]], 1);
}

__global__ void csr_scan_block_kernel()
{
    __shared__ int s[SCAN_BLK];
    int t = threadIdx.x;
    int i = blockIdx.x * SCAN_BLK + t;
    int v = (i < NNODES) ? g_deg[i] : 0;
    s[t] = v;
    __syncthreads();
#pragma unroll
    for (int off = 1; off < SCAN_BLK; off <<= 1) {
        int x = (t >= off) ? s[t - off] : 0;
        __syncthreads();
        s[t] += x;
        __syncthreads();
    }
    if (i < NNODES) g_rowptr[i] = s[t] - v;       // exclusive within block
    if (t == SCAN_BLK - 1) g_blocksum[blockIdx.x] = s[t];
}

__global__ void csr_scan_tops_kernel(int nblocks, int E)
{
    __shared__ int s[128];
    int t = threadIdx.x;                            // 128 threads
    int v = (t < nblocks) ? g_blocksum[t] : 0;
    s[t] = v;
    __syncthreads();
#pragma unroll
    for (int off = 1; off < 128; off <<= 1) {
        int x = (t >= off) ? s[t - off] : 0;
        __syncthreads();
        s[t] += x;
        __syncthreads();
    }
    g_blocksum[t] = s[t] - v;                       // exclusive block offsets
    if (t == 0) g_rowptr[NNODES] = E;
}

__global__ void csr_addoff_kernel()
{
    int i = blockIdx.x * SCAN_BLK + threadIdx.x;
    if (i < NNODES) g_rowptr[i] += g_blocksum[blockIdx.x];
}

__global__ void csr_fill_kernel(const int* __restrict__ srcp,
                                const int* __restrict__ dstp, int E)
{
    int e = blockIdx.x * blockDim.x + threadIdx.x;
    if (e >= E) return;
    int d = dstp[e];
    int p = atomicAdd(&g_fill[d], 1);
    g_csrc[g_rowptr[d] + p] = srcp[e];
}

// ----------------------------------------------------------------------------
// Per-node attention dots (warp per node) + zero BN stats for this layer
// ----------------------------------------------------------------------------
__global__ void alphadot_kernel(const float* __restrict__ h,
                                const float* __restrict__ a_s,
                                const float* __restrict__ a_d)
{
    int gtid = blockIdx.x * blockDim.x + threadIdx.x;
    if (gtid < 2 * HID) g_stats[gtid] = 0.f;

    int n = gtid >> 5;
    int lane = gtid & 31;
    if (n >= NNODES) return;

    float4 hv = *(const float4*)(h + (size_t)n * HID + lane * 4);
    float4 s4 = *(const float4*)(a_s + lane * 4);
    float4 d4 = *(const float4*)(a_d + lane * 4);
    float ss = hv.x * s4.x + hv.y * s4.y + hv.z * s4.z + hv.w * s4.w;
    float sd = hv.x * d4.x + hv.y * d4.y + hv.z * d4.z + hv.w * d4.w;
#pragma unroll
    for (int o = 16; o > 0; o >>= 1) {
        ss += __shfl_xor_sync(0xffffffffu, ss, o);
        sd += __shfl_xor_sync(0xffffffffu, sd, o);
    }
    if (lane == 0) {
        g_as[n] = ss;
        g_ad[n] = sd;
    }
}

// ----------------------------------------------------------------------------
// Fused segment softmax + aggregation: one warp per destination node.
// (Exact R4 structure — exps are warp-uniform, effectively free.)
// ----------------------------------------------------------------------------
__global__ void gat_node_kernel(const float* __restrict__ h,
                                const float* __restrict__ bias)
{
    int n = (blockIdx.x * blockDim.x + threadIdx.x) >> 5;
    int lane = threadIdx.x & 31;
    if (n >= NNODES) return;

    int beg = g_rowptr[n];
    int end = g_rowptr[n + 1];
    float adn = g_ad[n];
    float selfs = lrelu(g_as[n] + adn);

    // Pass 1: segment max (self-loop seeded)
    float m = selfs;
    for (int i = beg + lane; i < end; i += 32)
        m = fmaxf(m, lrelu(g_as[g_csrc[i]] + adn));
#pragma unroll
    for (int o = 16; o > 0; o >>= 1)
        m = fmaxf(m, __shfl_xor_sync(0xffffffffu, m, o));

    // Pass 2: exp-sum
    float sum = 0.f;
    for (int i = beg + lane; i < end; i += 32)
        sum += __expf(lrelu(g_as[g_csrc[i]] + adn) - m);
#pragma unroll
    for (int o = 16; o > 0; o >>= 1)
        sum += __shfl_xor_sync(0xffffffffu, sum, o);
    sum += __expf(selfs - m);
    float inv = __fdividef(1.f, sum);

    // Pass 3: weighted accumulate (lanes own 4 channels each)
    float cs = __expf(selfs - m) * inv;
    float4 hv = *(const float4*)(h + (size_t)n * HID + lane * 4);
    float4 acc;
    acc.x = cs * hv.x; acc.y = cs * hv.y; acc.z = cs * hv.z; acc.w = cs * hv.w;

    for (int i = beg; i < end; i++) {
        int s = g_csrc[i];                                   // broadcast load
        float c = __expf(lrelu(g_as[s] + adn) - m) * inv;
        float4 v = *(const float4*)(h + (size_t)s * HID + lane * 4);
        acc.x += c * v.x; acc.y += c * v.y; acc.z += c * v.z; acc.w += c * v.w;
    }

    float4 bv = *(const float4*)(bias + lane * 4);
    acc.x += bv.x; acc.y += bv.y; acc.z += bv.z; acc.w += bv.w;
    *(float4*)(g_out + (size_t)n * HID + lane * 4) = acc;
}

// ----------------------------------------------------------------------------
// BN stats: block-local per-channel sum/sumsq, one global atomic per channel
// ----------------------------------------------------------------------------
__global__ void bnstats_kernel()
{
    __shared__ float ssum[HID];
    __shared__ float ssq[HID];
    int t = threadIdx.x;
    int c = t & (HID - 1);
    int half = t >> 7;               // 0 or 1 (256 threads)
    int n0 = blockIdx.x * 128;

    float sum = 0.f, sq = 0.f;
    for (int i = half; i < 128; i += 2) {
        int n = n0 + i;
        if (n < NNODES) {
            float v = g_out[(size_t)n * HID + c];
            sum += v;
            sq  += v * v;
        }
    }
    if (half == 1) { ssum[c] = sum; ssq[c] = sq; }
    __syncthreads();
    if (half == 0) {
        sum += ssum[c];
        sq  += ssq[c];
        atomicAdd(&g_stats[c], sum);
        atomicAdd(&g_stats[HID + c], sq);
    }
}

// ----------------------------------------------------------------------------
// Finalize BN: fold mean/var/gamma/beta into per-channel scale+shift
// ----------------------------------------------------------------------------
__global__ void bnfinal_kernel(const float* __restrict__ gamma,
                               const float* __restrict__ beta)
{
    int c = threadIdx.x;                 // 128 threads
    float inv_n = 1.0f / (float)NNODES;
    float mean = g_stats[c] * inv_n;
    float var  = g_stats[HID + c] * inv_n - mean * mean;
    float sc = gamma[c] * rsqrtf(var + BN_EPS);
    g_bnsc[c] = sc;
    g_bnsh[c] = beta[c] - mean * sc;
}

// ----------------------------------------------------------------------------
extern "C" void kernel_launch(void* const* d_in, const int* in_sizes, int n_in,
                              void* d_out, int out_size)
{
    const float* x    = (const float*)d_in[0];
    const int*   ei   = (const int*)d_in[1];     // int32 (JAX x64 disabled)
    const float* W1   = (const float*)d_in[2];
    const float* as1  = (const float*)d_in[3];
    const float* ad1  = (const float*)d_in[4];
    const float* b1   = (const float*)d_in[5];
    const float* g1   = (const float*)d_in[6];
    const float* be1  = (const float*)d_in[7];
    const float* W2   = (const float*)d_in[8];
    const float* as2  = (const float*)d_in[9];
    const float* ad2  = (const float*)d_in[10];
    const float* b2   = (const float*)d_in[11];
    const float* g2   = (const float*)d_in[12];
    const float* be2  = (const float*)d_in[13];
    const float* Wc   = (const float*)d_in[14];
    const float* bc   = (const float*)d_in[15];
    float*       out  = (float*)d_out;

    int E = in_sizes[1] / 2;
    if (E > EMAX) E = EMAX;
    const int* srcp = ei;
    const int* dstp = ei + E;

    float* d_h;
    cudaGetSymbolAddress((void**)&d_h, g_h);
    float* d_agg;
    cudaGetSymbolAddress((void**)&d_agg, g_out);

    const int gemm_grid = (NNODES + 127) / 128;
    const int node_grid = (NNODES * 32 + 255) / 256;

    // CSR build interleaved with the (CSR-independent) layer-1 GEMM so the
    // ncu -s window lands on the GEMM instead of a scan kernel.
    csr_zero_kernel<<<(NNODES + 255) / 256, 256>>>();
    csr_count_kernel<<<(E + 255) / 256, 256>>>(dstp, E);
    csr_scan_block_kernel<<<NSCANBLK, SCAN_BLK>>>();
    mma_gemm_kernel<128, 128, 4, 2, false, false, false><<<gemm_grid, 256>>>(
        x, W1, nullptr, d_h, NNODES, FDIM, HID);                    // launch #4
    csr_scan_tops_kernel<<<1, 128>>>(NSCANBLK, E);
    csr_addoff_kernel<<<NSCANBLK, SCAN_BLK>>>();
    csr_fill_kernel<<<(E + 255) / 256, 256>>>(srcp, dstp, E);

    // ---- Layer 1 rest ----
    alphadot_kernel<<<node_grid, 256>>>(d_h, as1, ad1);
    gat_node_kernel<<<node_grid, 256>>>(d_h, b1);
    bnstats_kernel<<<(NNODES + 127) / 128, 256>>>();
    bnfinal_kernel<<<1, 128>>>(g1, be1);

    // ---- Layer 2 (A = BN(out1) applied inline in GEMM) ----
    mma_gemm_kernel<128, 128, 4, 2, false, false, true><<<gemm_grid, 256>>>(
        d_agg, W2, nullptr, d_h, NNODES, HID, HID);
    alphadot_kernel<<<node_grid, 256>>>(d_h, as2, ad2);
    gat_node_kernel<<<node_grid, 256>>>(d_h, b2);
    bnstats_kernel<<<(NNODES + 127) / 128, 256>>>();
    bnfinal_kernel<<<1, 128>>>(g2, be2);

    // ---- Classifier: out = BN(out2) @ Wc + bc ----
    mma_gemm_kernel<128, 64, 4, 2, true, true, true><<<gemm_grid, 256>>>(
        d_agg, Wc, bc, out, NNODES, HID, NCLS);
}

// round 7
// speedup vs baseline: 1.5955x; 1.1782x over previous
#include <cuda_runtime.h>
#include <cuda_bf16.h>
#include <cstdint>

// Problem constants (fixed by the reference)
#define NNODES 100000
#define FDIM   128
#define HID    128
#define NCLS   40
#define EMAX   1600000
#define NEG_SLOPE 0.2f
#define BN_EPS 1e-5f

#define SCAN_BLK 1024
#define NSCANBLK ((NNODES + SCAN_BLK - 1) / SCAN_BLK)   // 98

// ----------------------------------------------------------------------------
// Device scratch (static globals — no runtime allocation allowed)
// ----------------------------------------------------------------------------
__device__ float g_h[NNODES * HID];      // linear output of current layer
__device__ float g_out[NNODES * HID];    // GAT aggregation output (pre-BN)
__device__ float g_as[NNODES];
__device__ float g_ad[NNODES];
__device__ float g_stats[2 * HID];       // per-channel sum / sumsq
__device__ float g_bnsc[HID];            // folded BN scale (gamma * rstd)
__device__ float g_bnsh[HID];            // folded BN shift (beta - mean*scale)

// Prepacked bf16{hi,lo} operands, kp-major (kp = k/2 pair index)
__device__ uint2 g_Ap[64 * NNODES + 128];   // [kp][m], padded for tile overrun
__device__ uint2 g_Bp[64 * 128];            // [kp][n]

// CSR (dst -> list of src), rebuilt every launch (deterministic)
__device__ int g_deg[NNODES];
__device__ int g_fill[NNODES];
__device__ int g_rowptr[NNODES + 1];
__device__ int g_blocksum[128];
__device__ int g_csrc[EMAX];

// ----------------------------------------------------------------------------
__device__ __forceinline__ float lrelu(float x) {
    return x > 0.f ? x : NEG_SLOPE * x;
}

__device__ __forceinline__ unsigned bfpack(float lo, float hi) {
    __nv_bfloat162 p = __floats2bfloat162_rn(lo, hi);
    return *(unsigned*)&p;
}

// Split float pair (va, vb) into {hi_pack, lo_pack}
__device__ __forceinline__ uint2 split2(float va, float vb) {
    float a0 = __bfloat162float(__float2bfloat16_rn(va));
    float b0 = __bfloat162float(__float2bfloat16_rn(vb));
    return make_uint2(bfpack(a0, b0), bfpack(va - a0, vb - b0));
}

// bf16 mma m16n8k16: d = a*b + c
__device__ __forceinline__ void mma_bf16(float d[4], const unsigned a[4],
                                         const unsigned b[2], const float c[4]) {
    asm volatile(
        "mma.sync.aligned.m16n8k16.row.col.f32.bf16.bf16.f32 "
        "{%0,%1,%2,%3}, {%4,%5,%6,%7}, {%8,%9}, {%10,%11,%12,%13};"
        : "=f"(d[0]), "=f"(d[1]), "=f"(d[2]), "=f"(d[3])
        : "r"(a[0]), "r"(a[1]), "r"(a[2]), "r"(a[3]),
          "r"(b[0]), "r"(b[1]),
          "f"(c[0]), "f"(c[1]), "f"(c[2]), "f"(c[3]));
}

__device__ __forceinline__ uint32_t smem_u32(const void* p) {
    return (uint32_t)__cvta_generic_to_shared(p);
}

// ----------------------------------------------------------------------------
// Prepack A (activations): [m][k] float -> [kp][m] uint2 bf16{hi,lo}.
// Optional BN scale/shift + ReLU folded in. K = 128 fixed.
// ----------------------------------------------------------------------------
template<bool BNA>
__global__ void aprep_kernel(const float* __restrict__ A)
{
    __shared__ uint2 s[64][65];
    int m0 = blockIdx.x * 64;
    for (int i = threadIdx.x; i < 64 * 64; i += 256) {
        int r = i >> 6, kp = i & 63;
        float2 v = make_float2(0.f, 0.f);
        if (m0 + r < NNODES)
            v = *(const float2*)(A + (size_t)(m0 + r) * HID + 2 * kp);
        if (BNA) {
            int c = 2 * kp;
            v.x = fmaxf(v.x * g_bnsc[c] + g_bnsh[c], 0.f);
            v.y = fmaxf(v.y * g_bnsc[c + 1] + g_bnsh[c + 1], 0.f);
        }
        s[r][kp] = split2(v.x, v.y);
    }
    __syncthreads();
    for (int i = threadIdx.x; i < 64 * 64; i += 256) {
        int kp = i >> 6, r = i & 63;
        if (m0 + r < NNODES)
            g_Ap[(size_t)kp * NNODES + m0 + r] = s[r][kp];
    }
}

// ----------------------------------------------------------------------------
// Prepack B (weights): [k][n] float -> [kp][n] uint2 bf16{hi,lo}, n padded.
// ----------------------------------------------------------------------------
__global__ void bprep_kernel(const float* __restrict__ B, int K, int NC, int NPAD)
{
    int i = blockIdx.x * blockDim.x + threadIdx.x;
    if (i >= (K / 2) * NPAD) return;
    int kp = i / NPAD, n = i % NPAD;
    float be = 0.f, bo = 0.f;
    if (n < NC) {
        be = B[(size_t)(2 * kp) * NC + n];
        bo = B[(size_t)(2 * kp + 1) * NC + n];
    }
    g_Bp[i] = split2(be, bo);
}

// ----------------------------------------------------------------------------
// bf16x3 tensor-core GEMM on prepacked operands, cp.async double-buffered.
// C[M, NC] = A @ B (+bias). acc += a0b0 + a0b1 + a1b0  (~2^-17 accurate).
// ----------------------------------------------------------------------------
template<int BM, int BN, int NWM, int NWN, bool BIAS, bool NGUARD>
__global__ void __launch_bounds__(NWM * NWN * 32, 2)
mma_gemm_kernel(const uint2* __restrict__ Ap, const uint2* __restrict__ Bp,
                const float* __restrict__ bias, float* __restrict__ C,
                int M, int K, int NC, int NPAD)
{
    constexpr int THREADS = NWM * NWN * 32;
    constexpr int WM = BM / NWM;
    constexpr int WN = BN / NWN;
    constexpr int MT = WM / 16;
    constexpr int NT = WN / 8;
    constexpr int PAD = 2;

    __shared__ __align__(16) uint2 As[2][8][BM + PAD];
    __shared__ __align__(16) uint2 Bs[2][8][BN + PAD];

    const int tid    = threadIdx.x;
    const int warpId = tid >> 5;
    const int lane   = tid & 31;
    const int warpM  = warpId % NWM;
    const int warpN  = warpId / NWM;
    const int t      = lane & 3;
    const int g      = lane >> 2;
    const int rowBase = blockIdx.x * BM;
    const int NITER  = K / 16;

#define ISSUE_STAGE(st, buf) do {                                              \
    int kpb = (st) * 8;                                                        \
    _Pragma("unroll")                                                          \
    for (int u = tid; u < (BM * 8) / 2; u += THREADS) {                        \
        int kpl = u / (BM / 2); int mu = u % (BM / 2);                         \
        const void* gsrc = Ap + (size_t)(kpb + kpl) * M + rowBase + mu * 2;    \
        uint32_t d = smem_u32(&As[buf][kpl][mu * 2]);                          \
        asm volatile("cp.async.cg.shared.global [%0], [%1], 16;"               \
                     :: "r"(d), "l"(gsrc));                                    \
    }                                                                          \
    _Pragma("unroll")                                                          \
    for (int u = tid; u < (BN * 8) / 2; u += THREADS) {                        \
        int kpl = u / (BN / 2); int nu = u % (BN / 2);                         \
        const void* gsrc = Bp + (size_t)(kpb + kpl) * NPAD + nu * 2;           \
        uint32_t d = smem_u32(&Bs[buf][kpl][nu * 2]);                          \
        asm volatile("cp.async.cg.shared.global [%0], [%1], 16;"               \
                     :: "r"(d), "l"(gsrc));                                    \
    }                                                                          \
    asm volatile("cp.async.commit_group;");                                    \
} while (0)

    float acc[MT][NT][4];
#pragma unroll
    for (int i = 0; i < MT; i++)
#pragma unroll
        for (int j = 0; j < NT; j++)
#pragma unroll
            for (int r = 0; r < 4; r++) acc[i][j][r] = 0.f;

    ISSUE_STAGE(0, 0);

    for (int it = 0; it < NITER; ++it) {
        asm volatile("cp.async.wait_group 0;");
        __syncthreads();
        if (it + 1 < NITER) ISSUE_STAGE(it + 1, (it + 1) & 1);

        const int cur = it & 1;
        unsigned a0[MT][4], a1[MT][4];
#pragma unroll
        for (int mt = 0; mt < MT; mt++) {
            int mr = warpM * WM + mt * 16;
            uint2 v0 = As[cur][t][mr + g];
            uint2 v1 = As[cur][t][mr + g + 8];
            uint2 v2 = As[cur][t + 4][mr + g];
            uint2 v3 = As[cur][t + 4][mr + g + 8];
            a0[mt][0] = v0.x; a1[mt][0] = v0.y;
            a0[mt][1] = v1.x; a1[mt][1] = v1.y;
            a0[mt][2] = v2.x; a1[mt][2] = v2.y;
            a0[mt][3] = v3.x; a1[mt][3] = v3.y;
        }
        unsigned b0[NT][2], b1[NT][2];
#pragma unroll
        for (int nt = 0; nt < NT; nt++) {
            int nc0 = warpN * WN + nt * 8;
            uint2 w0 = Bs[cur][t][nc0 + g];
            uint2 w1 = Bs[cur][t + 4][nc0 + g];
            b0[nt][0] = w0.x; b1[nt][0] = w0.y;
            b0[nt][1] = w1.x; b1[nt][1] = w1.y;
        }
#pragma unroll
        for (int mt = 0; mt < MT; mt++)
#pragma unroll
            for (int nt = 0; nt < NT; nt++) {
                mma_bf16(acc[mt][nt], a0[mt], b1[nt], acc[mt][nt]);
                mma_bf16(acc[mt][nt], a1[mt], b0[nt], acc[mt][nt]);
                mma_bf16(acc[mt][nt], a0[mt], b0[nt], acc[mt][nt]);
            }
        __syncthreads();
    }
#undef ISSUE_STAGE

#pragma unroll
    for (int mt = 0; mt < MT; mt++) {
#pragma unroll
        for (int nt = 0; nt < NT; nt++) {
            int col = warpN * WN + nt * 8 + 2 * t;
            if (NGUARD && col >= NC) continue;
            float b0v = 0.f, b1v = 0.f;
            if (BIAS) { b0v = bias[col]; b1v = bias[col + 1]; }
            int row0 = rowBase + warpM * WM + mt * 16 + g;
            if (row0 < M) {
                float2 v = make_float2(acc[mt][nt][0] + b0v, acc[mt][nt][1] + b1v);
                *(float2*)(C + (size_t)row0 * NC + col) = v;
            }
            int row1 = row0 + 8;
            if (row1 < M) {
                float2 v = make_float2(acc[mt][nt][2] + b0v, acc[mt][nt][3] + b1v);
                *(float2*)(C + (size_t)row1 * NC + col) = v;
            }
        }
    }
}

// ----------------------------------------------------------------------------
// CSR build kernels (edge indices are int32)
// ----------------------------------------------------------------------------
__global__ void csr_zero_kernel()
{
    int i = blockIdx.x * blockDim.x + threadIdx.x;
    if (i < NNODES) { g_deg[i] = 0; g_fill[i] = 0; }
}

__global__ void csr_count_kernel(const int* __restrict__ dstp, int E)
{
    int e = blockIdx.x * blockDim.x + threadIdx.x;
    if (e < E) atomicAdd(&g_deg[dstp[e]], 1);
}

__global__ void csr_scan_block_kernel()
{
    __shared__ int s[SCAN_BLK];
    int t = threadIdx.x;
    int i = blockIdx.x * SCAN_BLK + t;
    int v = (i < NNODES) ? g_deg[i] : 0;
    s[t] = v;
    __syncthreads();
#pragma unroll
    for (int off = 1; off < SCAN_BLK; off <<= 1) {
        int x = (t >= off) ? s[t - off] : 0;
        __syncthreads();
        s[t] += x;
        __syncthreads();
    }
    if (i < NNODES) g_rowptr[i] = s[t] - v;       // exclusive within block
    if (t == SCAN_BLK - 1) g_blocksum[blockIdx.x] = s[t];
}

__global__ void csr_scan_tops_kernel(int nblocks, int E)
{
    __shared__ int s[128];
    int t = threadIdx.x;                            // 128 threads
    int v = (t < nblocks) ? g_blocksum[t] : 0;
    s[t] = v;
    __syncthreads();
#pragma unroll
    for (int off = 1; off < 128; off <<= 1) {
        int x = (t >= off) ? s[t - off] : 0;
        __syncthreads();
        s[t] += x;
        __syncthreads();
    }
    g_blocksum[t] = s[t] - v;                       // exclusive block offsets
    if (t == 0) g_rowptr[NNODES] = E;
}

__global__ void csr_addoff_kernel()
{
    int i = blockIdx.x * SCAN_BLK + threadIdx.x;
    if (i < NNODES) g_rowptr[i] += g_blocksum[blockIdx.x];
}

__global__ void csr_fill_kernel(const int* __restrict__ srcp,
                                const int* __restrict__ dstp, int E)
{
    int e = blockIdx.x * blockDim.x + threadIdx.x;
    if (e >= E) return;
    int d = dstp[e];
    int p = atomicAdd(&g_fill[d], 1);
    g_csrc[g_rowptr[d] + p] = srcp[e];
}

// ----------------------------------------------------------------------------
// Per-node attention dots (warp per node) + zero BN stats for this layer
// ----------------------------------------------------------------------------
__global__ void alphadot_kernel(const float* __restrict__ h,
                                const float* __restrict__ a_s,
                                const float* __restrict__ a_d)
{
    int gtid = blockIdx.x * blockDim.x + threadIdx.x;
    if (gtid < 2 * HID) g_stats[gtid] = 0.f;

    int n = gtid >> 5;
    int lane = gtid & 31;
    if (n >= NNODES) return;

    float4 hv = *(const float4*)(h + (size_t)n * HID + lane * 4);
    float4 s4 = *(const float4*)(a_s + lane * 4);
    float4 d4 = *(const float4*)(a_d + lane * 4);
    float ss = hv.x * s4.x + hv.y * s4.y + hv.z * s4.z + hv.w * s4.w;
    float sd = hv.x * d4.x + hv.y * d4.y + hv.z * d4.z + hv.w * d4.w;
#pragma unroll
    for (int o = 16; o > 0; o >>= 1) {
        ss += __shfl_xor_sync(0xffffffffu, ss, o);
        sd += __shfl_xor_sync(0xffffffffu, sd, o);
    }
    if (lane == 0) {
        g_as[n] = ss;
        g_ad[n] = sd;
    }
}

// ----------------------------------------------------------------------------
// Fused segment softmax + aggregation: one warp per destination node.
// ----------------------------------------------------------------------------
__global__ void gat_node_kernel(const float* __restrict__ h,
                                const float* __restrict__ bias)
{
    int n = (blockIdx.x * blockDim.x + threadIdx.x) >> 5;
    int lane = threadIdx.x & 31;
    if (n >= NNODES) return;

    int beg = g_rowptr[n];
    int end = g_rowptr[n + 1];
    float adn = g_ad[n];
    float selfs = lrelu(g_as[n] + adn);

    // Pass 1: segment max (self-loop seeded)
    float m = selfs;
    for (int i = beg + lane; i < end; i += 32)
        m = fmaxf(m, lrelu(g_as[g_csrc[i]] + adn));
#pragma unroll
    for (int o = 16; o > 0; o >>= 1)
        m = fmaxf(m, __shfl_xor_sync(0xffffffffu, m, o));

    // Pass 2: exp-sum
    float sum = 0.f;
    for (int i = beg + lane; i < end; i += 32)
        sum += __expf(lrelu(g_as[g_csrc[i]] + adn) - m);
#pragma unroll
    for (int o = 16; o > 0; o >>= 1)
        sum += __shfl_xor_sync(0xffffffffu, sum, o);
    sum += __expf(selfs - m);
    float inv = __fdividef(1.f, sum);

    // Pass 3: weighted accumulate (lanes own 4 channels each)
    float cs = __expf(selfs - m) * inv;
    float4 hv = *(const float4*)(h + (size_t)n * HID + lane * 4);
    float4 acc;
    acc.x = cs * hv.x; acc.y = cs * hv.y; acc.z = cs * hv.z; acc.w = cs * hv.w;

    for (int i = beg; i < end; i++) {
        int s = g_csrc[i];                                   // broadcast load
        float c = __expf(lrelu(g_as[s] + adn) - m) * inv;
        float4 v = *(const float4*)(h + (size_t)s * HID + lane * 4);
        acc.x += c * v.x; acc.y += c * v.y; acc.z += c * v.z; acc.w += c * v.w;
    }

    float4 bv = *(const float4*)(bias + lane * 4);
    acc.x += bv.x; acc.y += bv.y; acc.z += bv.z; acc.w += bv.w;
    *(float4*)(g_out + (size_t)n * HID + lane * 4) = acc;
}

// ----------------------------------------------------------------------------
// BN stats: block-local per-channel sum/sumsq, one global atomic per channel
// ----------------------------------------------------------------------------
__global__ void bnstats_kernel()
{
    __shared__ float ssum[HID];
    __shared__ float ssq[HID];
    int t = threadIdx.x;
    int c = t & (HID - 1);
    int half = t >> 7;               // 0 or 1 (256 threads)
    int n0 = blockIdx.x * 128;

    float sum = 0.f, sq = 0.f;
    for (int i = half; i < 128; i += 2) {
        int n = n0 + i;
        if (n < NNODES) {
            float v = g_out[(size_t)n * HID + c];
            sum += v;
            sq  += v * v;
        }
    }
    if (half == 1) { ssum[c] = sum; ssq[c] = sq; }
    __syncthreads();
    if (half == 0) {
        sum += ssum[c];
        sq  += ssq[c];
        atomicAdd(&g_stats[c], sum);
        atomicAdd(&g_stats[HID + c], sq);
    }
}

// ----------------------------------------------------------------------------
// Finalize BN: fold mean/var/gamma/beta into per-channel scale+shift
// ----------------------------------------------------------------------------
__global__ void bnfinal_kernel(const float* __restrict__ gamma,
                               const float* __restrict__ beta)
{
    int c = threadIdx.x;                 // 128 threads
    float inv_n = 1.0f / (float)NNODES;
    float mean = g_stats[c] * inv_n;
    float var  = g_stats[HID + c] * inv_n - mean * mean;
    float sc = gamma[c] * rsqrtf(var + BN_EPS);
    g_bnsc[c] = sc;
    g_bnsh[c] = beta[c] - mean * sc;
}

// ----------------------------------------------------------------------------
extern "C" void kernel_launch(void* const* d_in, const int* in_sizes, int n_in,
                              void* d_out, int out_size)
{
    const float* x    = (const float*)d_in[0];
    const int*   ei   = (const int*)d_in[1];     // int32 (JAX x64 disabled)
    const float* W1   = (const float*)d_in[2];
    const float* as1  = (const float*)d_in[3];
    const float* ad1  = (const float*)d_in[4];
    const float* b1   = (const float*)d_in[5];
    const float* g1   = (const float*)d_in[6];
    const float* be1  = (const float*)d_in[7];
    const float* W2   = (const float*)d_in[8];
    const float* as2  = (const float*)d_in[9];
    const float* ad2  = (const float*)d_in[10];
    const float* b2   = (const float*)d_in[11];
    const float* g2   = (const float*)d_in[12];
    const float* be2  = (const float*)d_in[13];
    const float* Wc   = (const float*)d_in[14];
    const float* bc   = (const float*)d_in[15];
    float*       out  = (float*)d_out;

    int E = in_sizes[1] / 2;
    if (E > EMAX) E = EMAX;
    const int* srcp = ei;
    const int* dstp = ei + E;

    float* d_h;
    cudaGetSymbolAddress((void**)&d_h, g_h);
    float* d_agg;
    cudaGetSymbolAddress((void**)&d_agg, g_out);
    uint2* d_Ap;
    cudaGetSymbolAddress((void**)&d_Ap, g_Ap);
    uint2* d_Bp;
    cudaGetSymbolAddress((void**)&d_Bp, g_Bp);

    const int gemm_grid  = (NNODES + 127) / 128;
    const int node_grid  = (NNODES * 32 + 255) / 256;
    const int aprep_grid = (NNODES + 63) / 64;

    // ---- Prepack layer-1 operands; gemm1 at launch #4 for ncu window ----
    csr_zero_kernel<<<(NNODES + 255) / 256, 256>>>();
    aprep_kernel<false><<<aprep_grid, 256>>>(x);
    bprep_kernel<<<(64 * 128 + 255) / 256, 256>>>(W1, HID, HID, 128);
    mma_gemm_kernel<128, 128, 4, 2, false, false><<<gemm_grid, 256>>>(
        d_Ap, d_Bp, nullptr, d_h, NNODES, HID, HID, 128);
    // ---- CSR build (independent of GEMM) ----
    csr_count_kernel<<<(E + 255) / 256, 256>>>(dstp, E);
    csr_scan_block_kernel<<<NSCANBLK, SCAN_BLK>>>();
    csr_scan_tops_kernel<<<1, 128>>>(NSCANBLK, E);
    csr_addoff_kernel<<<NSCANBLK, SCAN_BLK>>>();
    csr_fill_kernel<<<(E + 255) / 256, 256>>>(srcp, dstp, E);

    // ---- Layer 1 rest ----
    alphadot_kernel<<<node_grid, 256>>>(d_h, as1, ad1);
    gat_node_kernel<<<node_grid, 256>>>(d_h, b1);
    bnstats_kernel<<<(NNODES + 127) / 128, 256>>>();
    bnfinal_kernel<<<1, 128>>>(g1, be1);

    // ---- Layer 2: prepack BN(out1) + W2, GEMM, attention ----
    aprep_kernel<true><<<aprep_grid, 256>>>(d_agg);
    bprep_kernel<<<(64 * 128 + 255) / 256, 256>>>(W2, HID, HID, 128);
    mma_gemm_kernel<128, 128, 4, 2, false, false><<<gemm_grid, 256>>>(
        d_Ap, d_Bp, nullptr, d_h, NNODES, HID, HID, 128);
    alphadot_kernel<<<node_grid, 256>>>(d_h, as2, ad2);
    gat_node_kernel<<<node_grid, 256>>>(d_h, b2);
    bnstats_kernel<<<(NNODES + 127) / 128, 256>>>();
    bnfinal_kernel<<<1, 128>>>(g2, be2);

    // ---- Classifier: out = BN(out2) @ Wc + bc ----
    aprep_kernel<true><<<aprep_grid, 256>>>(d_agg);
    bprep_kernel<<<(64 * 64 + 255) / 256, 256>>>(Wc, HID, NCLS, 64);
    mma_gemm_kernel<128, 64, 4, 2, true, true><<<gemm_grid, 256>>>(
        d_Ap, d_Bp, bc, out, NNODES, HID, NCLS, 64);
}

// round 9
// speedup vs baseline: 1.7191x; 1.0774x over previous
#include <cuda_runtime.h>
#include <cuda_bf16.h>
#include <cstdint>

// Problem constants (fixed by the reference)
#define NNODES 100000
#define FDIM   128
#define HID    128
#define NCLS   40
#define EMAX   1600000
#define NEG_SLOPE 0.2f
#define BN_EPS 1e-5f

#define SCAN_BLK 1024
#define NSCANBLK ((NNODES + SCAN_BLK - 1) / SCAN_BLK)   // 98

// ----------------------------------------------------------------------------
// Device scratch (static globals — no runtime allocation allowed)
// ----------------------------------------------------------------------------
__device__ float g_h[NNODES * HID];      // linear output of current layer
__device__ float g_out[NNODES * HID];    // GAT aggregation output (pre-BN)
__device__ float g_as[NNODES];
__device__ float g_ad[NNODES];
__device__ float g_se[EMAX];             // cached per-slot edge scores
__device__ float g_stats[2 * HID];       // per-channel sum / sumsq
__device__ float g_bnsc[HID];            // folded BN scale (gamma * rstd)
__device__ float g_bnsh[HID];            // folded BN shift (beta - mean*scale)

// Prepacked bf16{hi,lo} operands, kp-major (kp = k/2 pair index)
__device__ uint2 g_Ap[64 * NNODES + 128];   // [kp][m], padded for tile overrun
__device__ uint2 g_Bp[64 * 128];            // [kp][n]

// CSR (dst -> list of src), rebuilt every launch (deterministic)
__device__ int g_deg[NNODES];
__device__ int g_fill[NNODES];
__device__ int g_rowptr[NNODES + 1];
__device__ int g_blocksum[128];
__device__ int g_csrc[EMAX];

// ----------------------------------------------------------------------------
__device__ __forceinline__ float lrelu(float x) {
    return x > 0.f ? x : NEG_SLOPE * x;
}

__device__ __forceinline__ unsigned bfpack(float lo, float hi) {
    __nv_bfloat162 p = __floats2bfloat162_rn(lo, hi);
    return *(unsigned*)&p;
}

__device__ __forceinline__ uint2 split2(float va, float vb) {
    float a0 = __bfloat162float(__float2bfloat16_rn(va));
    float b0 = __bfloat162float(__float2bfloat16_rn(vb));
    return make_uint2(bfpack(a0, b0), bfpack(va - a0, vb - b0));
}

__device__ __forceinline__ void mma_bf16(float d[4], const unsigned a[4],
                                         const unsigned b[2], const float c[4]) {
    asm volatile(
        "mma.sync.aligned.m16n8k16.row.col.f32.bf16.bf16.f32 "
        "{%0,%1,%2,%3}, {%4,%5,%6,%7}, {%8,%9}, {%10,%11,%12,%13};"
        : "=f"(d[0]), "=f"(d[1]), "=f"(d[2]), "=f"(d[3])
        : "r"(a[0]), "r"(a[1]), "r"(a[2]), "r"(a[3]),
          "r"(b[0]), "r"(b[1]),
          "f"(c[0]), "f"(c[1]), "f"(c[2]), "f"(c[3]));
}

__device__ __forceinline__ uint32_t smem_u32(const void* p) {
    return (uint32_t)__cvta_generic_to_shared(p);
}

// ----------------------------------------------------------------------------
// Prepack A: [m][k] float -> [kp][m] uint2 bf16{hi,lo}. Optional BN+ReLU.
// ----------------------------------------------------------------------------
template<bool BNA>
__global__ void aprep_kernel(const float* __restrict__ A)
{
    __shared__ uint2 s[64][65];
    int m0 = blockIdx.x * 64;
    for (int i = threadIdx.x; i < 64 * 64; i += 256) {
        int r = i >> 6, kp = i & 63;
        float2 v = make_float2(0.f, 0.f);
        if (m0 + r < NNODES)
            v = *(const float2*)(A + (size_t)(m0 + r) * HID + 2 * kp);
        if (BNA) {
            int c = 2 * kp;
            v.x = fmaxf(v.x * g_bnsc[c] + g_bnsh[c], 0.f);
            v.y = fmaxf(v.y * g_bnsc[c + 1] + g_bnsh[c + 1], 0.f);
        }
        s[r][kp] = split2(v.x, v.y);
    }
    __syncthreads();
    for (int i = threadIdx.x; i < 64 * 64; i += 256) {
        int kp = i >> 6, r = i & 63;
        if (m0 + r < NNODES)
            g_Ap[(size_t)kp * NNODES + m0 + r] = s[r][kp];
    }
}

// ----------------------------------------------------------------------------
// Prepack B: [k][n] float -> [kp][n] uint2 bf16{hi,lo}, n padded.
// ----------------------------------------------------------------------------
__global__ void bprep_kernel(const float* __restrict__ B, int K, int NC, int NPAD)
{
    int i = blockIdx.x * blockDim.x + threadIdx.x;
    if (i >= (K / 2) * NPAD) return;
    int kp = i / NPAD, n = i % NPAD;
    float be = 0.f, bo = 0.f;
    if (n < NC) {
        be = B[(size_t)(2 * kp) * NC + n];
        bo = B[(size_t)(2 * kp + 1) * NC + n];
    }
    g_Bp[i] = split2(be, bo);
}

// ----------------------------------------------------------------------------
// bf16x3 GEMM, 3-stage cp.async pipeline. Optional fused alpha-dot epilogue
// (DOTS): writes g_as/g_ad = C_row · a_s / a_d, removing alphadot kernel.
// ----------------------------------------------------------------------------
template<int BM, int BN, int NWM, int NWN, bool BIAS, bool NGUARD, bool DOTS>
__global__ void __launch_bounds__(NWM * NWN * 32, 2)
mma_gemm_kernel(const uint2* __restrict__ Ap, const uint2* __restrict__ Bp,
                const float* __restrict__ bias,
                const float* __restrict__ avs, const float* __restrict__ avd,
                float* __restrict__ C, int M, int K, int NC, int NPAD)
{
    constexpr int THREADS = NWM * NWN * 32;
    constexpr int WM = BM / NWM;
    constexpr int WN = BN / NWN;
    constexpr int MT = WM / 16;
    constexpr int NT = WN / 8;
    constexpr int PAD = 2;

    extern __shared__ __align__(16) char dyn[];
    uint2 (*As)[8][BM + PAD] = (uint2(*)[8][BM + PAD])dyn;
    uint2 (*Bs)[8][BN + PAD] =
        (uint2(*)[8][BN + PAD])(dyn + 3 * 8 * (BM + PAD) * sizeof(uint2));
    float* sdot = (float*)(dyn + 3 * 8 * (BM + PAD) * sizeof(uint2)
                               + 3 * 8 * (BN + PAD) * sizeof(uint2));

    const int tid    = threadIdx.x;
    const int warpId = tid >> 5;
    const int lane   = tid & 31;
    const int warpM  = warpId % NWM;
    const int warpN  = warpId / NWM;
    const int t      = lane & 3;
    const int g      = lane >> 2;
    const int rowBase = blockIdx.x * BM;
    const int NITER  = K / 16;

#define ISSUE_STAGE(st, buf) do {                                              \
    int kpb = (st) * 8;                                                        \
    _Pragma("unroll")                                                          \
    for (int u = tid; u < (BM * 8) / 2; u += THREADS) {                        \
        int kpl = u / (BM / 2); int mu = u % (BM / 2);                         \
        const void* gsrc = Ap + (size_t)(kpb + kpl) * M + rowBase + mu * 2;    \
        uint32_t d = smem_u32(&As[buf][kpl][mu * 2]);                          \
        asm volatile("cp.async.cg.shared.global [%0], [%1], 16;"               \
                     :: "r"(d), "l"(gsrc));                                    \
    }                                                                          \
    _Pragma("unroll")                                                          \
    for (int u = tid; u < (BN * 8) / 2; u += THREADS) {                        \
        int kpl = u / (BN / 2); int nu = u % (BN / 2);                         \
        const void* gsrc = Bp + (size_t)(kpb + kpl) * NPAD + nu * 2;           \
        uint32_t d = smem_u32(&Bs[buf][kpl][nu * 2]);                          \
        asm volatile("cp.async.cg.shared.global [%0], [%1], 16;"               \
                     :: "r"(d), "l"(gsrc));                                    \
    }                                                                          \
    asm volatile("cp.async.commit_group;");                                    \
} while (0)

    float acc[MT][NT][4];
#pragma unroll
    for (int i = 0; i < MT; i++)
#pragma unroll
        for (int j = 0; j < NT; j++)
#pragma unroll
            for (int r = 0; r < 4; r++) acc[i][j][r] = 0.f;

    ISSUE_STAGE(0, 0);
    ISSUE_STAGE(1, 1);

    for (int it = 0; it < NITER; ++it) {
        if (it + 1 < NITER)
            asm volatile("cp.async.wait_group 1;");
        else
            asm volatile("cp.async.wait_group 0;");
        __syncthreads();
        if (it + 2 < NITER) ISSUE_STAGE(it + 2, (it + 2) % 3);

        const int cur = it % 3;
        unsigned a0[MT][4], a1[MT][4];
#pragma unroll
        for (int mt = 0; mt < MT; mt++) {
            int mr = warpM * WM + mt * 16;
            uint2 v0 = As[cur][t][mr + g];
            uint2 v1 = As[cur][t][mr + g + 8];
            uint2 v2 = As[cur][t + 4][mr + g];
            uint2 v3 = As[cur][t + 4][mr + g + 8];
            a0[mt][0] = v0.x; a1[mt][0] = v0.y;
            a0[mt][1] = v1.x; a1[mt][1] = v1.y;
            a0[mt][2] = v2.x; a1[mt][2] = v2.y;
            a0[mt][3] = v3.x; a1[mt][3] = v3.y;
        }
        unsigned b0[NT][2], b1[NT][2];
#pragma unroll
        for (int nt = 0; nt < NT; nt++) {
            int nc0 = warpN * WN + nt * 8;
            uint2 w0 = Bs[cur][t][nc0 + g];
            uint2 w1 = Bs[cur][t + 4][nc0 + g];
            b0[nt][0] = w0.x; b1[nt][0] = w0.y;
            b0[nt][1] = w1.x; b1[nt][1] = w1.y;
        }
#pragma unroll
        for (int mt = 0; mt < MT; mt++)
#pragma unroll
            for (int nt = 0; nt < NT; nt++) {
                mma_bf16(acc[mt][nt], a0[mt], b1[nt], acc[mt][nt]);
                mma_bf16(acc[mt][nt], a1[mt], b0[nt], acc[mt][nt]);
                mma_bf16(acc[mt][nt], a0[mt], b0[nt], acc[mt][nt]);
            }
    }
#undef ISSUE_STAGE

    // ---- C store ----
#pragma unroll
    for (int mt = 0; mt < MT; mt++) {
#pragma unroll
        for (int nt = 0; nt < NT; nt++) {
            int col = warpN * WN + nt * 8 + 2 * t;
            if (NGUARD && col >= NC) continue;
            float b0v = 0.f, b1v = 0.f;
            if (BIAS) { b0v = bias[col]; b1v = bias[col + 1]; }
            int row0 = rowBase + warpM * WM + mt * 16 + g;
            if (row0 < M) {
                float2 v = make_float2(acc[mt][nt][0] + b0v, acc[mt][nt][1] + b1v);
                *(float2*)(C + (size_t)row0 * NC + col) = v;
            }
            int row1 = row0 + 8;
            if (row1 < M) {
                float2 v = make_float2(acc[mt][nt][2] + b0v, acc[mt][nt][3] + b1v);
                *(float2*)(C + (size_t)row1 * NC + col) = v;
            }
        }
    }

    // ---- Fused alpha-dot epilogue ----
    if (DOTS) {
        float psA[MT], pdA[MT], psB[MT], pdB[MT];
#pragma unroll
        for (int mt = 0; mt < MT; mt++) {
            psA[mt] = 0.f; pdA[mt] = 0.f; psB[mt] = 0.f; pdB[mt] = 0.f;
        }
#pragma unroll
        for (int nt = 0; nt < NT; nt++) {
            int col = warpN * WN + nt * 8 + 2 * t;
            float s0 = avs[col], s1 = avs[col + 1];
            float d0 = avd[col], d1 = avd[col + 1];
#pragma unroll
            for (int mt = 0; mt < MT; mt++) {
                psA[mt] += acc[mt][nt][0] * s0 + acc[mt][nt][1] * s1;
                pdA[mt] += acc[mt][nt][0] * d0 + acc[mt][nt][1] * d1;
                psB[mt] += acc[mt][nt][2] * s0 + acc[mt][nt][3] * s1;
                pdB[mt] += acc[mt][nt][2] * d0 + acc[mt][nt][3] * d1;
            }
        }
#pragma unroll
        for (int o = 1; o <= 2; o <<= 1) {
#pragma unroll
            for (int mt = 0; mt < MT; mt++) {
                psA[mt] += __shfl_xor_sync(0xffffffffu, psA[mt], o);
                pdA[mt] += __shfl_xor_sync(0xffffffffu, pdA[mt], o);
                psB[mt] += __shfl_xor_sync(0xffffffffu, psB[mt], o);
                pdB[mt] += __shfl_xor_sync(0xffffffffu, pdB[mt], o);
            }
        }
        if (t == 0) {
#pragma unroll
            for (int mt = 0; mt < MT; mt++) {
                int rA = warpM * WM + mt * 16 + g;
                sdot[(rA * NWN + warpN) * 2 + 0] = psA[mt];
                sdot[(rA * NWN + warpN) * 2 + 1] = pdA[mt];
                sdot[((rA + 8) * NWN + warpN) * 2 + 0] = psB[mt];
                sdot[((rA + 8) * NWN + warpN) * 2 + 1] = pdB[mt];
            }
        }
        __syncthreads();
        for (int r = tid; r < BM; r += THREADS) {
            int grow = rowBase + r;
            if (grow < M) {
                float ss = 0.f, dd = 0.f;
#pragma unroll
                for (int wn = 0; wn < NWN; wn++) {
                    ss += sdot[(r * NWN + wn) * 2 + 0];
                    dd += sdot[(r * NWN + wn) * 2 + 1];
                }
                g_as[grow] = ss;
                g_ad[grow] = dd;
            }
        }
    }
}

// ----------------------------------------------------------------------------
// CSR build kernels (edge indices are int32)
// ----------------------------------------------------------------------------
__global__ void csr_zero_kernel()
{
    int i = blockIdx.x * blockDim.x + threadIdx.x;
    if (i < NNODES) { g_deg[i] = 0; g_fill[i] = 0; }
    if (i < 2 * HID) g_stats[i] = 0.f;
}

__global__ void csr_count_kernel(const int* __restrict__ dstp, int E)
{
    int e = blockIdx.x * blockDim.x + threadIdx.x;
    if (e < E) atomicAdd(&g_deg[dstp[e]], 1);
}

__global__ void csr_scan_block_kernel()
{
    __shared__ int s[SCAN_BLK];
    int t = threadIdx.x;
    int i = blockIdx.x * SCAN_BLK + t;
    int v = (i < NNODES) ? g_deg[i] : 0;
    s[t] = v;
    __syncthreads();
#pragma unroll
    for (int off = 1; off < SCAN_BLK; off <<= 1) {
        int x = (t >= off) ? s[t - off] : 0;
        __syncthreads();
        s[t] += x;
        __syncthreads();
    }
    if (i < NNODES) g_rowptr[i] = s[t] - v;       // exclusive within block
    if (t == SCAN_BLK - 1) g_blocksum[blockIdx.x] = s[t];
}

__global__ void csr_scan_tops_kernel(int nblocks, int E)
{
    __shared__ int s[128];
    int t = threadIdx.x;                            // 128 threads
    int v = (t < nblocks) ? g_blocksum[t] : 0;
    s[t] = v;
    __syncthreads();
#pragma unroll
    for (int off = 1; off < 128; off <<= 1) {
        int x = (t >= off) ? s[t - off] : 0;
        __syncthreads();
        s[t] += x;
        __syncthreads();
    }
    g_blocksum[t] = s[t] - v;                       // exclusive block offsets
    if (t == 0) g_rowptr[NNODES] = E;
}

__global__ void csr_addoff_kernel()
{
    int i = blockIdx.x * SCAN_BLK + threadIdx.x;
    if (i < NNODES) g_rowptr[i] += g_blocksum[blockIdx.x];
}

__global__ void csr_fill_kernel(const int* __restrict__ srcp,
                                const int* __restrict__ dstp, int E)
{
    int e = blockIdx.x * blockDim.x + threadIdx.x;
    if (e >= E) return;
    int d = dstp[e];
    int p = atomicAdd(&g_fill[d], 1);
    g_csrc[g_rowptr[d] + p] = srcp[e];
}

// ----------------------------------------------------------------------------
// Fused segment softmax + aggregation + bias + BN-stats.
// One warp per destination node; scores cached in g_se (coalesced reuse).
// ----------------------------------------------------------------------------
__global__ void gat_node_kernel(const float* __restrict__ h,
                                const float* __restrict__ bias)
{
    __shared__ float red[8][HID];

    const int tid  = threadIdx.x;
    const int w    = tid >> 5;
    const int lane = tid & 31;
    const int n    = (blockIdx.x * blockDim.x + tid) >> 5;

    float4 outv = make_float4(0.f, 0.f, 0.f, 0.f);

    if (n < NNODES) {
        const int beg = g_rowptr[n];
        const int end = g_rowptr[n + 1];
        const float adn = g_ad[n];
        const float selfs = lrelu(g_as[n] + adn);

        // Pass 1: gather scores once, cache, segment max
        float m = selfs;
        for (int i = beg + lane; i < end; i += 32) {
            float s = lrelu(g_as[g_csrc[i]] + adn);
            g_se[i] = s;
            m = fmaxf(m, s);
        }
#pragma unroll
        for (int o = 16; o > 0; o >>= 1)
            m = fmaxf(m, __shfl_xor_sync(0xffffffffu, m, o));
        __syncwarp();

        // Pass 2: exp-sum (coalesced reads of cached scores)
        float sum = 0.f;
        for (int i = beg + lane; i < end; i += 32)
            sum += __expf(g_se[i] - m);
#pragma unroll
        for (int o = 16; o > 0; o >>= 1)
            sum += __shfl_xor_sync(0xffffffffu, sum, o);
        float eself = __expf(selfs - m);
        float inv = __fdividef(1.f, sum + eself);

        // Pass 3: weighted accumulate (lanes own 4 channels each)
        float cs = eself * inv;
        float4 hv = *(const float4*)(h + (size_t)n * HID + (lane << 2));
        float4 acc;
        acc.x = cs * hv.x; acc.y = cs * hv.y; acc.z = cs * hv.z; acc.w = cs * hv.w;

        for (int j = beg; j < end; j++) {
            float c = __expf(g_se[j] - m) * inv;       // broadcast scalar load
            int s = g_csrc[j];
            float4 v = *(const float4*)(h + (size_t)s * HID + (lane << 2));
            acc.x += c * v.x; acc.y += c * v.y; acc.z += c * v.z; acc.w += c * v.w;
        }

        float4 bv = *(const float4*)(bias + (lane << 2));
        outv.x = acc.x + bv.x; outv.y = acc.y + bv.y;
        outv.z = acc.z + bv.z; outv.w = acc.w + bv.w;
        *(float4*)(g_out + (size_t)n * HID + (lane << 2)) = outv;
    }

    // BN-stats: per-warp values into smem, block-reduce, 256 atomics/block
    int c0 = lane << 2;
    red[w][c0 + 0] = outv.x;
    red[w][c0 + 1] = outv.y;
    red[w][c0 + 2] = outv.z;
    red[w][c0 + 3] = outv.w;
    __syncthreads();

    int c = tid & (HID - 1);
    bool issq = tid >= HID;
    float a = 0.f;
#pragma unroll
    for (int w2 = 0; w2 < 8; w2++) {
        float v = red[w2][c];
        a += issq ? v * v : v;
    }
    atomicAdd(&g_stats[issq ? HID + c : c], a);
}

// ----------------------------------------------------------------------------
// Finalize BN: fold into scale+shift; re-zero stats for next layer/replay
// ----------------------------------------------------------------------------
__global__ void bnfinal_kernel(const float* __restrict__ gamma,
                               const float* __restrict__ beta)
{
    int c = threadIdx.x;                 // 128 threads
    float inv_n = 1.0f / (float)NNODES;
    float mean = g_stats[c] * inv_n;
    float var  = g_stats[HID + c] * inv_n - mean * mean;
    float sc = gamma[c] * rsqrtf(var + BN_EPS);
    g_bnsc[c] = sc;
    g_bnsh[c] = beta[c] - mean * sc;
    g_stats[c] = 0.f;
    g_stats[HID + c] = 0.f;
}

// ----------------------------------------------------------------------------
extern "C" void kernel_launch(void* const* d_in, const int* in_sizes, int n_in,
                              void* d_out, int out_size)
{
    const float* x    = (const float*)d_in[0];
    const int*   ei   = (const int*)d_in[1];     // int32 (JAX x64 disabled)
    const float* W1   = (const float*)d_in[2];
    const float* as1  = (const float*)d_in[3];
    const float* ad1  = (const float*)d_in[4];
    const float* b1   = (const float*)d_in[5];
    const float* g1   = (const float*)d_in[6];
    const float* be1  = (const float*)d_in[7];
    const float* W2   = (const float*)d_in[8];
    const float* as2  = (const float*)d_in[9];
    const float* ad2  = (const float*)d_in[10];
    const float* b2   = (const float*)d_in[11];
    const float* g2   = (const float*)d_in[12];
    const float* be2  = (const float*)d_in[13];
    const float* Wc   = (const float*)d_in[14];
    const float* bc   = (const float*)d_in[15];
    float*       out  = (float*)d_out;

    int E = in_sizes[1] / 2;
    if (E > EMAX) E = EMAX;
    const int* srcp = ei;
    const int* dstp = ei + E;

    float* d_h;
    cudaGetSymbolAddress((void**)&d_h, g_h);
    float* d_agg;
    cudaGetSymbolAddress((void**)&d_agg, g_out);
    uint2* d_Ap;
    cudaGetSymbolAddress((void**)&d_Ap, g_Ap);
    uint2* d_Bp;
    cudaGetSymbolAddress((void**)&d_Bp, g_Bp);

    // Dynamic smem sizes (3-stage pipeline + dot-reduction scratch)
    const int smem128 = (3 * 8 * 130 + 3 * 8 * 130) * (int)sizeof(uint2)
                      + 128 * 2 * 2 * (int)sizeof(float);
    const int smem64  = (3 * 8 * 130 + 3 * 8 * 66) * (int)sizeof(uint2)
                      + 128 * 2 * 2 * (int)sizeof(float);
    cudaFuncSetAttribute(mma_gemm_kernel<128, 128, 4, 2, false, false, true>,
                         cudaFuncAttributeMaxDynamicSharedMemorySize, smem128);
    cudaFuncSetAttribute(mma_gemm_kernel<128, 64, 4, 2, true, true, false>,
                         cudaFuncAttributeMaxDynamicSharedMemorySize, smem64);

    const int gemm_grid  = (NNODES + 127) / 128;
    const int node_grid  = (NNODES * 32 + 255) / 256;
    const int aprep_grid = (NNODES + 63) / 64;

    // ---- Prepack layer-1 operands; gemm1 at launch #4 for ncu window ----
    csr_zero_kernel<<<(NNODES + 255) / 256, 256>>>();
    aprep_kernel<false><<<aprep_grid, 256>>>(x);
    bprep_kernel<<<(64 * 128 + 255) / 256, 256>>>(W1, HID, HID, 128);
    mma_gemm_kernel<128, 128, 4, 2, false, false, true>
        <<<gemm_grid, 256, smem128>>>(d_Ap, d_Bp, nullptr, as1, ad1,
                                      d_h, NNODES, HID, HID, 128);
    // ---- CSR build (independent of GEMM) ----
    csr_count_kernel<<<(E + 255) / 256, 256>>>(dstp, E);
    csr_scan_block_kernel<<<NSCANBLK, SCAN_BLK>>>();
    csr_scan_tops_kernel<<<1, 128>>>(NSCANBLK, E);
    csr_addoff_kernel<<<NSCANBLK, SCAN_BLK>>>();
    csr_fill_kernel<<<(E + 255) / 256, 256>>>(srcp, dstp, E);

    // ---- Layer 1 attention + BN fold ----
    gat_node_kernel<<<node_grid, 256>>>(d_h, b1);
    bnfinal_kernel<<<1, 128>>>(g1, be1);

    // ---- Layer 2 ----
    aprep_kernel<true><<<aprep_grid, 256>>>(d_agg);
    bprep_kernel<<<(64 * 128 + 255) / 256, 256>>>(W2, HID, HID, 128);
    mma_gemm_kernel<128, 128, 4, 2, false, false, true>
        <<<gemm_grid, 256, smem128>>>(d_Ap, d_Bp, nullptr, as2, ad2,
                                      d_h, NNODES, HID, HID, 128);
    gat_node_kernel<<<node_grid, 256>>>(d_h, b2);
    bnfinal_kernel<<<1, 128>>>(g2, be2);

    // ---- Classifier: out = BN(out2) @ Wc + bc ----
    aprep_kernel<true><<<aprep_grid, 256>>>(d_agg);
    bprep_kernel<<<(64 * 64 + 255) / 256, 256>>>(Wc, HID, NCLS, 64);
    mma_gemm_kernel<128, 64, 4, 2, true, true, false>
        <<<gemm_grid, 256, smem64>>>(d_Ap, d_Bp, bc, nullptr, nullptr,
                                     out, NNODES, HID, NCLS, 64);
}